// round 14
// baseline (speedup 1.0000x reference)
#include <cuda_runtime.h>
#include <cuda_fp16.h>
#include <cuda_bf16.h>

#define Nn   100000
#define Ee   1600000
#define FIN  128
#define FHID 32
#define FOUT 2

// ---------------- scratch (__device__ globals; no allocation) ----------------
// g_cnt / g_bar rely on zero-init at module load; g_cnt is re-zeroed in the
// final phase each call; g_bar is a monotonic barrier counter (round-up logic
// makes it self-consistent across calls/replays).
__device__ __align__(16) __half g_g1h[Nn * FHID];   // dinv-scaled h1 (fp16)
__device__ __align__(16) __half g_agg1h[Nn * FHID]; // layer-1 accum (fp16)
__device__ __align__(8)  float g_g2[Nn * FOUT];     // dinv-scaled h2
__device__ __align__(8)  float g_agg2[Nn * FOUT];   // layer-2 accum
__device__ int g_cnt[Nn];                            // in-degree (no self loop)
__device__ unsigned g_bar;                           // grid barrier counter

// grid-wide barrier: arrive (release) + spin to next multiple of nblocks
__device__ __forceinline__ void gridbar(int nb) {
    __syncthreads();
    if (threadIdx.x == 0) {
        __threadfence();
        unsigned arrival = atomicAdd(&g_bar, 1u) + 1u;
        unsigned target  = ((arrival + (unsigned)nb - 1u) / (unsigned)nb) * (unsigned)nb;
        while (atomicAdd(&g_bar, 0u) < target) __nanosleep(64);
        __threadfence();
    }
    __syncthreads();
}

// ---------------- K1: degree histogram (int4 vectorized) ----------------
__global__ void k_hist(const int* __restrict__ ei) {
    int t = blockIdx.x * blockDim.x + threadIdx.x;
    if (t >= Ee / 4) return;
    int4 c = reinterpret_cast<const int4*>(ei + Ee)[t];
    atomicAdd(&g_cnt[c.x], 1);
    atomicAdd(&g_cnt[c.y], 1);
    atomicAdd(&g_cnt[c.z], 1);
    atomicAdd(&g_cnt[c.w], 1);
}

// ---------------- K2: g1 = dinv*(x@W1) via fma.rn.f32x2 ----------------
// 8 nodes/warp, 64 nodes/block; fp16 store + agg1 self-loop init (proven R9)
__global__ void __launch_bounds__(256) k_gemm1(const float* __restrict__ x,
                                               const float* __restrict__ W1) {
    __shared__ __align__(16) float sWp[FIN * FHID]; // 16 KB paired W1
    __shared__ __align__(16) float sx[64 * FIN];    // 32 KB x-rows
    int tid = threadIdx.x;
    for (int i = tid; i < FIN * FHID; i += 256) {
        int k = i >> 5, lane = i & 31;
        sWp[(((k >> 1) * 32) + lane) * 2 + (k & 1)] = W1[i];
    }
    int nodeBase = blockIdx.x * 64;
    {
        const float4* x4 = reinterpret_cast<const float4*>(x);
        float4* sx4 = reinterpret_cast<float4*>(sx);
        for (int i = tid; i < 2048; i += 256) {
            int node = nodeBase + (i >> 5);
            sx4[i] = (node < Nn) ? x4[(size_t)node * 32 + (i & 31)]
                                 : make_float4(0.f, 0.f, 0.f, 0.f);
        }
    }
    __syncthreads();

    int w = tid >> 5, lane = tid & 31;
    int n0 = w * 8;
    const ulonglong2* sxq = reinterpret_cast<const ulonglong2*>(sx);     // 32 per row
    const unsigned long long* sWq = reinterpret_cast<const unsigned long long*>(sWp);
    unsigned long long acc[8];
#pragma unroll
    for (int i = 0; i < 8; i++) acc[i] = 0ULL;
#pragma unroll
    for (int kp2 = 0; kp2 < 32; kp2++) {
        unsigned long long w0 = sWq[(2 * kp2 + 0) * 32 + lane];
        unsigned long long w1 = sWq[(2 * kp2 + 1) * 32 + lane];
#pragma unroll
        for (int i = 0; i < 8; i++) {
            ulonglong2 xv = sxq[(n0 + i) * 32 + kp2];
            asm("fma.rn.f32x2 %0, %1, %2, %0;" : "+l"(acc[i]) : "l"(xv.x), "l"(w0));
            asm("fma.rn.f32x2 %0, %1, %2, %0;" : "+l"(acc[i]) : "l"(xv.y), "l"(w1));
        }
    }
#pragma unroll
    for (int i = 0; i < 8; i++) {
        int gn = nodeBase + n0 + i;
        if (gn < Nn) {
            float lo, hi;
            asm("mov.b64 {%0,%1}, %2;" : "=f"(lo), "=f"(hi) : "l"(acc[i]));
            float dinv = rsqrtf((float)g_cnt[gn] + 1.0f);
            __half h = __float2half_rn(dinv * (lo + hi));
            g_g1h  [gn * FHID + lane] = h;
            g_agg1h[gn * FHID + lane] = h;          // self-loop init
        }
    }
}

// ---------------- K3: persistent tail {scatter1, layer2, scatter2, final} ----------------
// All phases are low-register / near-zero smem -> high occupancy for the
// latency-bound scatter phases; 3 internal barriers replace 3 launch gaps.
__global__ void __launch_bounds__(256, 6) k_post(
    const int* __restrict__ ei, const float* __restrict__ b1,
    const float* __restrict__ W2, const float* __restrict__ b2,
    float* __restrict__ out, int nblocks)
{
    __shared__ float sW[FHID * FOUT];   // 64 floats
    __shared__ float sb[FHID];          // 32 floats
    const int tid = threadIdx.x;
    const int gt  = blockIdx.x * 256 + tid;
    const int GT  = nblocks * 256;
    if (tid < FHID * FOUT) sW[tid] = W2[tid];
    if (tid < FHID)        sb[tid] = b1[tid];
    __syncthreads();

    // ---- P2: layer-1 edge scatter (fp16 v4.f16x2 RED), 4 units/iter for MLP ----
    {
        const unsigned total = (unsigned)Ee * 4u;
        const unsigned S = (unsigned)GT;
        unsigned t = (unsigned)gt;
        for (; t + 3u * S < total; t += 4u * S) {
#pragma unroll
            for (int u = 0; u < 4; u++) {
                unsigned tt = t + (unsigned)u * S;
                int e = tt >> 2, j = tt & 3;
                int r = ei[e], c = ei[Ee + e];
                uint4 v = reinterpret_cast<const uint4*>(g_g1h)[r * 4 + j];
                __half* dst = g_agg1h + c * FHID + j * 8;
                asm volatile("red.global.add.noftz.v4.f16x2 [%0], {%1,%2,%3,%4};"
                             :: "l"(dst), "r"(v.x), "r"(v.y), "r"(v.z), "r"(v.w) : "memory");
            }
        }
        for (; t < total; t += S) {
            int e = t >> 2, j = t & 3;
            int r = ei[e], c = ei[Ee + e];
            uint4 v = reinterpret_cast<const uint4*>(g_g1h)[r * 4 + j];
            __half* dst = g_agg1h + c * FHID + j * 8;
            asm volatile("red.global.add.noftz.v4.f16x2 [%0], {%1,%2,%3,%4};"
                         :: "l"(dst), "r"(v.x), "r"(v.y), "r"(v.z), "r"(v.w) : "memory");
        }
    }
    gridbar(nblocks);

    // ---- P3: layer2 thread-per-node ----
    for (int n = gt; n < Nn; n += GT) {
        float dinv = rsqrtf((float)g_cnt[n] + 1.0f);
        const uint4* row = reinterpret_cast<const uint4*>(g_agg1h) + n * 4;
        float p0 = 0.f, p1 = 0.f;
#pragma unroll
        for (int q = 0; q < 4; q++) {
            uint4 v = row[q];
            unsigned u[4] = {v.x, v.y, v.z, v.w};
#pragma unroll
            for (int h = 0; h < 4; h++) {
                float2 f = __half22float2(*reinterpret_cast<const __half2*>(&u[h]));
                int k = q * 8 + h * 2;
                float a0 = fmaxf(fmaf(dinv, f.x, sb[k + 0]), 0.f);
                float a1 = fmaxf(fmaf(dinv, f.y, sb[k + 1]), 0.f);
                p0 = fmaf(a0, sW[2 * k + 0], fmaf(a1, sW[2 * k + 2], p0));
                p1 = fmaf(a0, sW[2 * k + 1], fmaf(a1, sW[2 * k + 3], p1));
            }
        }
        float2 g = make_float2(dinv * p0, dinv * p1);
        reinterpret_cast<float2*>(g_g2)[n]   = g;
        reinterpret_cast<float2*>(g_agg2)[n] = g;   // self-loop init
    }
    gridbar(nblocks);

    // ---- P4: layer-2 edge scatter (fp32 float2 RED, 2 edges/iter) ----
    for (int t = gt; t < Ee / 2; t += GT) {
        int2 r = reinterpret_cast<const int2*>(ei)[t];
        int2 c = reinterpret_cast<const int2*>(ei + Ee)[t];
        float2 v0 = reinterpret_cast<const float2*>(g_g2)[r.x];
        float2 v1 = reinterpret_cast<const float2*>(g_g2)[r.y];
        atomicAdd(reinterpret_cast<float2*>(g_agg2) + c.x, v0);
        atomicAdd(reinterpret_cast<float2*>(g_agg2) + c.y, v1);
    }
    gridbar(nblocks);

    // ---- P5: finalize + log_softmax + reset g_cnt ----
    for (int n = gt; n < Nn; n += GT) {
        float dinv = rsqrtf((float)g_cnt[n] + 1.0f);
        float2 s = reinterpret_cast<const float2*>(g_agg2)[n];
        float o0 = dinv * s.x + b2[0];
        float o1 = dinv * s.y + b2[1];
        float m = fmaxf(o0, o1);
        float lse = m + logf(expf(o0 - m) + expf(o1 - m));
        reinterpret_cast<float2*>(out)[n] = make_float2(o0 - lse, o1 - lse);
        g_cnt[n] = 0;
    }
}

// ---------------- launch ----------------
extern "C" void kernel_launch(void* const* d_in, const int* in_sizes, int n_in,
                              void* d_out, int out_size) {
    const float* x  = (const float*)d_in[0];
    const int*   ei = (const int*)d_in[1];   // int32 on the wire
    const float* W1 = (const float*)d_in[2];
    const float* b1 = (const float*)d_in[3];
    const float* W2 = (const float*)d_in[4];
    const float* b2 = (const float*)d_in[5];
    float* out = (float*)d_out;

    int dev = 0; cudaGetDevice(&dev);
    int nsm = 148;
    cudaDeviceGetAttribute(&nsm, cudaDevAttrMultiProcessorCount, dev);
    int occ3 = 1;
    cudaOccupancyMaxActiveBlocksPerMultiprocessor(&occ3, k_post, 256, 0);
    if (occ3 < 1) occ3 = 1;
    int b3 = nsm * occ3;                      // co-resident for gridbar

    const int T = 256;
    k_hist <<<(Ee / 4 + T - 1) / T, T>>>(ei);
    k_gemm1<<<(Nn + 63) / 64, T>>>(x, W1);
    k_post <<<b3, T>>>(ei, b1, W2, b2, out, b3);
}

// round 15
// speedup vs baseline: 1.2608x; 1.2608x over previous
#include <cuda_runtime.h>
#include <cuda_fp16.h>
#include <cuda_bf16.h>

// Problem constants (fixed shapes per reference)
#define Nn   100000
#define Ee   1600000
#define FIN  128
#define FHID 32
#define FOUT 2

// ---------------- scratch (__device__ globals; no allocation) ----------------
// g_cnt relies on zero-init at module load; k_final re-zeroes it every call.
__device__ __align__(16) __half g_g1h[Nn * FHID];   // dinv-scaled h1 (fp16)   6.4 MB
__device__ __align__(16) __half g_agg1h[Nn * FHID]; // layer-1 accum (fp16)    6.4 MB
__device__ __align__(8)  float g_g2[Nn * FOUT];     // dinv-scaled h2          0.8 MB
__device__ __align__(8)  float g_agg2[Nn * FOUT];   // layer-2 accum           0.8 MB
__device__ int g_cnt[Nn];                            // in-degree (no self loop)

// ---------------- kernels ----------------

// degree histogram: 4 independent int4 loads per thread (MLP=4), 16 REDs
__global__ void k_hist(const int* __restrict__ ei) {
    const int N = Ee / 16;                       // 100000 threads, 4 strips
    int t = blockIdx.x * blockDim.x + threadIdx.x;
    if (t >= N) return;
    const int4* c4 = reinterpret_cast<const int4*>(ei + Ee);
    int4 a = c4[t];
    int4 b = c4[t + N];
    int4 c = c4[t + 2 * N];
    int4 d = c4[t + 3 * N];
    atomicAdd(&g_cnt[a.x], 1); atomicAdd(&g_cnt[a.y], 1);
    atomicAdd(&g_cnt[a.z], 1); atomicAdd(&g_cnt[a.w], 1);
    atomicAdd(&g_cnt[b.x], 1); atomicAdd(&g_cnt[b.y], 1);
    atomicAdd(&g_cnt[b.z], 1); atomicAdd(&g_cnt[b.w], 1);
    atomicAdd(&g_cnt[c.x], 1); atomicAdd(&g_cnt[c.y], 1);
    atomicAdd(&g_cnt[c.z], 1); atomicAdd(&g_cnt[c.w], 1);
    atomicAdd(&g_cnt[d.x], 1); atomicAdd(&g_cnt[d.y], 1);
    atomicAdd(&g_cnt[d.z], 1); atomicAdd(&g_cnt[d.w], 1);
}

// g1 = dinv * (x @ W1) via packed fma.rn.f32x2; 8 nodes/warp, 64 nodes/block.
// Stores fp16 g1 and initializes agg1 with the self-loop term. (proven R9/R10)
__global__ void __launch_bounds__(256) k_gemm1(const float* __restrict__ x,
                                               const float* __restrict__ W1) {
    __shared__ __align__(16) float sWp[FIN * FHID]; // paired: u64[p*32+lane]={W[2p],W[2p+1]}  16 KB
    __shared__ __align__(16) float sx[64 * FIN];    // 64 x-rows                               32 KB
    int tid = threadIdx.x;
    for (int i = tid; i < FIN * FHID; i += 256) {
        int k = i >> 5, lane = i & 31;
        sWp[(((k >> 1) * 32) + lane) * 2 + (k & 1)] = W1[i];
    }
    int nodeBase = blockIdx.x * 64;
    {
        const float4* x4 = reinterpret_cast<const float4*>(x);
        float4* sx4 = reinterpret_cast<float4*>(sx);
        for (int i = tid; i < 2048; i += 256) {
            int node = nodeBase + (i >> 5);
            sx4[i] = (node < Nn) ? x4[(size_t)node * 32 + (i & 31)]
                                 : make_float4(0.f, 0.f, 0.f, 0.f);
        }
    }
    __syncthreads();

    int w = tid >> 5, lane = tid & 31;
    int n0 = w * 8;                                   // local node base
    const ulonglong2* sxq = reinterpret_cast<const ulonglong2*>(sx);      // 32 per 128-float row
    const unsigned long long* sWq = reinterpret_cast<const unsigned long long*>(sWp);

    unsigned long long acc[8];
#pragma unroll
    for (int i = 0; i < 8; i++) acc[i] = 0ULL;        // {0.f, 0.f}

#pragma unroll
    for (int kp2 = 0; kp2 < 32; kp2++) {              // covers k = 4*kp2 .. 4*kp2+3
        unsigned long long w0 = sWq[(2 * kp2 + 0) * 32 + lane];
        unsigned long long w1 = sWq[(2 * kp2 + 1) * 32 + lane];
#pragma unroll
        for (int i = 0; i < 8; i++) {
            ulonglong2 xv = sxq[(n0 + i) * 32 + kp2]; // row stride = 32 ulonglong2
            asm("fma.rn.f32x2 %0, %1, %2, %0;" : "+l"(acc[i]) : "l"(xv.x), "l"(w0));
            asm("fma.rn.f32x2 %0, %1, %2, %0;" : "+l"(acc[i]) : "l"(xv.y), "l"(w1));
        }
    }

#pragma unroll
    for (int i = 0; i < 8; i++) {
        int gn = nodeBase + n0 + i;
        if (gn < Nn) {
            float lo, hi;
            asm("mov.b64 {%0,%1}, %2;" : "=f"(lo), "=f"(hi) : "l"(acc[i]));
            float dinv = rsqrtf((float)g_cnt[gn] + 1.0f);
            __half h = __float2half_rn(dinv * (lo + hi));
            g_g1h  [gn * FHID + lane] = h;
            g_agg1h[gn * FHID + lane] = h;            // self-loop init
        }
    }
}

// layer-1 edge scatter (fp16): 4 lanes per edge, 16B gather + v4.f16x2 RED (proven)
__global__ void k_scatter1(const int* __restrict__ ei) {
    unsigned int t = blockIdx.x * blockDim.x + threadIdx.x;
    if (t >= (unsigned int)Ee * 4u) return;
    int e = t >> 2;
    int j = t & 3;
    int r = ei[e];
    int c = ei[Ee + e];
    uint4 v = reinterpret_cast<const uint4*>(g_g1h)[r * 4 + j];   // 8 halves
    __half* dst = g_agg1h + c * FHID + j * 8;
    asm volatile("red.global.add.noftz.v4.f16x2 [%0], {%1,%2,%3,%4};"
                 :: "l"(dst), "r"(v.x), "r"(v.y), "r"(v.z), "r"(v.w) : "memory");
}

// a1 = relu(dinv*agg1 + b1); g2 = dinv*(a1 @ W2); agg2 init = g2 (self loop)
// thread per node: 4x LDG.128 row read, 64 FMAs, W2/b1 via smem broadcast (proven)
__global__ void __launch_bounds__(256) k_layer2(const float* __restrict__ b1,
                                                const float* __restrict__ W2) {
    __shared__ float sW[FHID * FOUT];   // 64 floats
    __shared__ float sb[FHID];          // 32 floats
    int tid = threadIdx.x;
    if (tid < FHID * FOUT) sW[tid] = W2[tid];
    if (tid < FHID)        sb[tid] = b1[tid];
    __syncthreads();

    int n = blockIdx.x * 256 + tid;
    if (n >= Nn) return;
    float dinv = rsqrtf((float)g_cnt[n] + 1.0f);
    const uint4* row = reinterpret_cast<const uint4*>(g_agg1h) + n * 4;
    float p0 = 0.f, p1 = 0.f;
#pragma unroll
    for (int q = 0; q < 4; q++) {
        uint4 v = row[q];
        unsigned u[4] = {v.x, v.y, v.z, v.w};
#pragma unroll
        for (int h = 0; h < 4; h++) {
            float2 f = __half22float2(*reinterpret_cast<const __half2*>(&u[h]));
            int k = q * 8 + h * 2;
            float a0 = fmaxf(fmaf(dinv, f.x, sb[k + 0]), 0.f);
            float a1 = fmaxf(fmaf(dinv, f.y, sb[k + 1]), 0.f);
            p0 = fmaf(a0, sW[2 * k + 0], fmaf(a1, sW[2 * k + 2], p0));
            p1 = fmaf(a0, sW[2 * k + 1], fmaf(a1, sW[2 * k + 3], p1));
        }
    }
    float2 g = make_float2(dinv * p0, dinv * p1);
    reinterpret_cast<float2*>(g_g2)[n]   = g;
    reinterpret_cast<float2*>(g_agg2)[n] = g;   // self-loop init
}

// layer-2 edge scatter: 4 edges/thread (int4 indices, 4 independent gathers)
__global__ void k_scatter2(const int* __restrict__ ei) {
    int t = blockIdx.x * blockDim.x + threadIdx.x;
    if (t >= Ee / 4) return;
    int4 r = reinterpret_cast<const int4*>(ei)[t];
    int4 c = reinterpret_cast<const int4*>(ei + Ee)[t];
    float2 v0 = reinterpret_cast<const float2*>(g_g2)[r.x];
    float2 v1 = reinterpret_cast<const float2*>(g_g2)[r.y];
    float2 v2 = reinterpret_cast<const float2*>(g_g2)[r.z];
    float2 v3 = reinterpret_cast<const float2*>(g_g2)[r.w];
    atomicAdd(reinterpret_cast<float2*>(g_agg2) + c.x, v0);
    atomicAdd(reinterpret_cast<float2*>(g_agg2) + c.y, v1);
    atomicAdd(reinterpret_cast<float2*>(g_agg2) + c.z, v2);
    atomicAdd(reinterpret_cast<float2*>(g_agg2) + c.w, v3);
}

// finalize: o = dinv*agg2 + b2; log_softmax; then reset g_cnt for next call
__global__ void k_final(const float* __restrict__ b2, float* __restrict__ out) {
    int n = blockIdx.x * blockDim.x + threadIdx.x;
    if (n >= Nn) return;
    float dinv = rsqrtf((float)g_cnt[n] + 1.0f);
    float2 s = reinterpret_cast<const float2*>(g_agg2)[n];
    float o0 = dinv * s.x + b2[0];
    float o1 = dinv * s.y + b2[1];
    float m = fmaxf(o0, o1);
    float lse = m + logf(expf(o0 - m) + expf(o1 - m));
    reinterpret_cast<float2*>(out)[n] = make_float2(o0 - lse, o1 - lse);
    g_cnt[n] = 0;                       // restore zero invariant for next call
}

// ---------------- launch ----------------
extern "C" void kernel_launch(void* const* d_in, const int* in_sizes, int n_in,
                              void* d_out, int out_size) {
    const float* x  = (const float*)d_in[0];
    const int*   ei = (const int*)d_in[1];   // int32 on the wire
    const float* W1 = (const float*)d_in[2];
    const float* b1 = (const float*)d_in[3];
    const float* W2 = (const float*)d_in[4];
    const float* b2 = (const float*)d_in[5];
    float* out = (float*)d_out;

    const int T = 256;
    k_hist    <<<(Ee / 16 + T - 1) / T, T>>>(ei);
    k_gemm1   <<<(Nn + 63) / 64, T>>>(x, W1);
    k_scatter1<<<((unsigned)Ee * 4u) / T, T>>>(ei);       // exact: 6.4M/256
    k_layer2  <<<(Nn + T - 1) / T, T>>>(b1, W2);
    k_scatter2<<<(Ee / 4 + T - 1) / T, T>>>(ei);
    k_final   <<<(Nn + T - 1) / T, T>>>(b2, out);
}

// round 16
// speedup vs baseline: 1.2776x; 1.0133x over previous
#include <cuda_runtime.h>
#include <cuda_fp16.h>
#include <cuda_bf16.h>

// Problem constants (fixed shapes per reference)
#define Nn   100000
#define Ee   1600000
#define FIN  128
#define FHID 32
#define FOUT 2

// ---------------- scratch (__device__ globals; no allocation) ----------------
// g_cnt relies on zero-init at module load; k_final re-zeroes it every call.
__device__ __align__(16) __half g_g1h[Nn * FHID];   // UNSCALED h1 (fp16)      6.4 MB
__device__ __align__(16) __half g_agg1h[Nn * FHID]; // layer-1 accum (fp16)    6.4 MB
__device__ __align__(8)  float g_g2[Nn * FOUT];     // dinv-scaled h2          0.8 MB
__device__ __align__(8)  float g_agg2[Nn * FOUT];   // layer-2 accum           0.8 MB
__device__ int    g_cnt[Nn];                         // in-degree (no self loop)
__device__ __half g_dinvh[Nn];                       // fp16 dinv for scatter1

// ---------------- K1: block-specialized hist + gemm (independent work) ------
// 5-block stripes: 4 gemm-role blocks : 1 hist-role block.
// gemm role: h1 = x @ W1 (UNSCALED) via fma.rn.f32x2, 8 nodes/warp, 64/block;
//            stores fp16 h1 and zeroes agg1 (self-loop applied in k_layer2).
// hist role: degree histogram, 4 independent int4 loads (MLP=4), 16 REDs.
#define GEMM_BLKS 1563                   // ceil(100000/64)
#define HIST_BLKS 391                    // ceil((Ee/16)/256)
#define HG_GRID   (5 * 391)              // 1955

__global__ void __launch_bounds__(256) k_histgemm(const float* __restrict__ x,
                                                  const float* __restrict__ W1,
                                                  const int* __restrict__ ei) {
    __shared__ __align__(16) float sWp[FIN * FHID]; // 16 KB paired W1
    __shared__ __align__(16) float sx[64 * FIN];    // 32 KB x-rows
    int bid = blockIdx.x;
    int tid = threadIdx.x;

    if ((bid % 5) == 4) {
        // ---- hist role ----
        int histId = bid / 5;                        // 0..390
        const int N = Ee / 16;                       // 100000
        int t = histId * 256 + tid;
        if (t >= N) return;
        const int4* c4 = reinterpret_cast<const int4*>(ei + Ee);
        int4 a = c4[t];
        int4 b = c4[t + N];
        int4 c = c4[t + 2 * N];
        int4 d = c4[t + 3 * N];
        atomicAdd(&g_cnt[a.x], 1); atomicAdd(&g_cnt[a.y], 1);
        atomicAdd(&g_cnt[a.z], 1); atomicAdd(&g_cnt[a.w], 1);
        atomicAdd(&g_cnt[b.x], 1); atomicAdd(&g_cnt[b.y], 1);
        atomicAdd(&g_cnt[b.z], 1); atomicAdd(&g_cnt[b.w], 1);
        atomicAdd(&g_cnt[c.x], 1); atomicAdd(&g_cnt[c.y], 1);
        atomicAdd(&g_cnt[c.z], 1); atomicAdd(&g_cnt[c.w], 1);
        atomicAdd(&g_cnt[d.x], 1); atomicAdd(&g_cnt[d.y], 1);
        atomicAdd(&g_cnt[d.z], 1); atomicAdd(&g_cnt[d.w], 1);
        return;
    }

    // ---- gemm role ----
    int gemmId = (bid / 5) * 4 + (bid % 5);          // 0..1563
    if (gemmId >= GEMM_BLKS) return;

    for (int i = tid; i < FIN * FHID; i += 256) {
        int k = i >> 5, lane = i & 31;
        sWp[(((k >> 1) * 32) + lane) * 2 + (k & 1)] = W1[i];
    }
    int nodeBase = gemmId * 64;
    {
        const float4* x4 = reinterpret_cast<const float4*>(x);
        float4* sx4 = reinterpret_cast<float4*>(sx);
        for (int i = tid; i < 2048; i += 256) {
            int node = nodeBase + (i >> 5);
            sx4[i] = (node < Nn) ? x4[(size_t)node * 32 + (i & 31)]
                                 : make_float4(0.f, 0.f, 0.f, 0.f);
        }
    }
    __syncthreads();

    int w = tid >> 5, lane = tid & 31;
    int n0 = w * 8;
    const ulonglong2* sxq = reinterpret_cast<const ulonglong2*>(sx);      // 32 per row
    const unsigned long long* sWq = reinterpret_cast<const unsigned long long*>(sWp);

    unsigned long long acc[8];
#pragma unroll
    for (int i = 0; i < 8; i++) acc[i] = 0ULL;
#pragma unroll
    for (int kp2 = 0; kp2 < 32; kp2++) {
        unsigned long long w0 = sWq[(2 * kp2 + 0) * 32 + lane];
        unsigned long long w1 = sWq[(2 * kp2 + 1) * 32 + lane];
#pragma unroll
        for (int i = 0; i < 8; i++) {
            ulonglong2 xv = sxq[(n0 + i) * 32 + kp2];
            asm("fma.rn.f32x2 %0, %1, %2, %0;" : "+l"(acc[i]) : "l"(xv.x), "l"(w0));
            asm("fma.rn.f32x2 %0, %1, %2, %0;" : "+l"(acc[i]) : "l"(xv.y), "l"(w1));
        }
    }
#pragma unroll
    for (int i = 0; i < 8; i++) {
        int gn = nodeBase + n0 + i;
        if (gn < Nn) {
            float lo, hi;
            asm("mov.b64 {%0,%1}, %2;" : "=f"(lo), "=f"(hi) : "l"(acc[i]));
            g_g1h  [gn * FHID + lane] = __float2half_rn(lo + hi);  // UNSCALED h1
            g_agg1h[gn * FHID + lane] = __ushort_as_half(0);       // zero accum
        }
    }
}

// ---------------- K2: dinv table (fp16) ----------------
__global__ void k_dinv() {
    int n = blockIdx.x * blockDim.x + threadIdx.x;
    if (n >= Nn) return;
    g_dinvh[n] = __float2half_rn(rsqrtf((float)g_cnt[n] + 1.0f));
}

// ---------------- K3: layer-1 edge scatter (fp16, on-the-fly source scale) --
// 4 lanes per edge: 16B gather, scale by dinv[r] (HMUL2 x4), v4.f16x2 RED
__global__ void k_scatter1(const int* __restrict__ ei) {
    unsigned int t = blockIdx.x * blockDim.x + threadIdx.x;
    if (t >= (unsigned int)Ee * 4u) return;
    int e = t >> 2;
    int j = t & 3;
    int r = ei[e];
    int c = ei[Ee + e];
    __half2 d2 = __half2half2(g_dinvh[r]);           // broadcast within 4-lane group
    uint4 v = reinterpret_cast<const uint4*>(g_g1h)[r * 4 + j];   // 8 halves
    __half2* vh = reinterpret_cast<__half2*>(&v);
    vh[0] = __hmul2(vh[0], d2);
    vh[1] = __hmul2(vh[1], d2);
    vh[2] = __hmul2(vh[2], d2);
    vh[3] = __hmul2(vh[3], d2);
    __half* dst = g_agg1h + c * FHID + j * 8;
    asm volatile("red.global.add.noftz.v4.f16x2 [%0], {%1,%2,%3,%4};"
                 :: "l"(dst), "r"(v.x), "r"(v.y), "r"(v.z), "r"(v.w) : "memory");
}

// ---------------- K4: layer2 thread-per-node ----------------
// a = relu(dinv*(agg + dinv*h1) + b1); g2 = dinv*(a @ W2); agg2 init = g2
__global__ void __launch_bounds__(256) k_layer2(const float* __restrict__ b1,
                                                const float* __restrict__ W2) {
    __shared__ float sW[FHID * FOUT];   // 64 floats
    __shared__ float sb[FHID];          // 32 floats
    int tid = threadIdx.x;
    if (tid < FHID * FOUT) sW[tid] = W2[tid];
    if (tid < FHID)        sb[tid] = b1[tid];
    __syncthreads();

    int n = blockIdx.x * 256 + tid;
    if (n >= Nn) return;
    float dinv = rsqrtf((float)g_cnt[n] + 1.0f);
    const uint4* arow = reinterpret_cast<const uint4*>(g_agg1h) + n * 4;
    const uint4* hrow = reinterpret_cast<const uint4*>(g_g1h)   + n * 4;
    float p0 = 0.f, p1 = 0.f;
#pragma unroll
    for (int q = 0; q < 4; q++) {
        uint4 va = arow[q];
        uint4 vh = hrow[q];
        unsigned ua[4] = {va.x, va.y, va.z, va.w};
        unsigned uh[4] = {vh.x, vh.y, vh.z, vh.w};
#pragma unroll
        for (int h = 0; h < 4; h++) {
            float2 fa = __half22float2(*reinterpret_cast<const __half2*>(&ua[h]));
            float2 fh = __half22float2(*reinterpret_cast<const __half2*>(&uh[h]));
            int k = q * 8 + h * 2;
            float s0 = fmaf(dinv, fh.x, fa.x);       // agg + dinv*h1 (self loop)
            float s1 = fmaf(dinv, fh.y, fa.y);
            float a0 = fmaxf(fmaf(dinv, s0, sb[k + 0]), 0.f);
            float a1 = fmaxf(fmaf(dinv, s1, sb[k + 1]), 0.f);
            p0 = fmaf(a0, sW[2 * k + 0], fmaf(a1, sW[2 * k + 2], p0));
            p1 = fmaf(a0, sW[2 * k + 1], fmaf(a1, sW[2 * k + 3], p1));
        }
    }
    float2 g = make_float2(dinv * p0, dinv * p1);
    reinterpret_cast<float2*>(g_g2)[n]   = g;
    reinterpret_cast<float2*>(g_agg2)[n] = g;        // self-loop init
}

// ---------------- K5: layer-2 edge scatter (4 edges/thread) ----------------
__global__ void k_scatter2(const int* __restrict__ ei) {
    int t = blockIdx.x * blockDim.x + threadIdx.x;
    if (t >= Ee / 4) return;
    int4 r = reinterpret_cast<const int4*>(ei)[t];
    int4 c = reinterpret_cast<const int4*>(ei + Ee)[t];
    float2 v0 = reinterpret_cast<const float2*>(g_g2)[r.x];
    float2 v1 = reinterpret_cast<const float2*>(g_g2)[r.y];
    float2 v2 = reinterpret_cast<const float2*>(g_g2)[r.z];
    float2 v3 = reinterpret_cast<const float2*>(g_g2)[r.w];
    atomicAdd(reinterpret_cast<float2*>(g_agg2) + c.x, v0);
    atomicAdd(reinterpret_cast<float2*>(g_agg2) + c.y, v1);
    atomicAdd(reinterpret_cast<float2*>(g_agg2) + c.z, v2);
    atomicAdd(reinterpret_cast<float2*>(g_agg2) + c.w, v3);
}

// ---------------- K6: finalize + log_softmax + reset g_cnt ----------------
__global__ void k_final(const float* __restrict__ b2, float* __restrict__ out) {
    int n = blockIdx.x * blockDim.x + threadIdx.x;
    if (n >= Nn) return;
    float dinv = rsqrtf((float)g_cnt[n] + 1.0f);
    float2 s = reinterpret_cast<const float2*>(g_agg2)[n];
    float o0 = dinv * s.x + b2[0];
    float o1 = dinv * s.y + b2[1];
    float m = fmaxf(o0, o1);
    float lse = m + logf(expf(o0 - m) + expf(o1 - m));
    reinterpret_cast<float2*>(out)[n] = make_float2(o0 - lse, o1 - lse);
    g_cnt[n] = 0;                       // restore zero invariant for next call
}

// ---------------- launch ----------------
extern "C" void kernel_launch(void* const* d_in, const int* in_sizes, int n_in,
                              void* d_out, int out_size) {
    const float* x  = (const float*)d_in[0];
    const int*   ei = (const int*)d_in[1];   // int32 on the wire
    const float* W1 = (const float*)d_in[2];
    const float* b1 = (const float*)d_in[3];
    const float* W2 = (const float*)d_in[4];
    const float* b2 = (const float*)d_in[5];
    float* out = (float*)d_out;

    const int T = 256;
    k_histgemm<<<HG_GRID, T>>>(x, W1, ei);
    k_dinv    <<<(Nn + T - 1) / T, T>>>();
    k_scatter1<<<((unsigned)Ee * 4u) / T, T>>>(ei);       // exact: 6.4M/256
    k_layer2  <<<(Nn + T - 1) / T, T>>>(b1, W2);
    k_scatter2<<<(Ee / 4 + T - 1) / T, T>>>(ei);
    k_final   <<<(Nn + T - 1) / T, T>>>(b2, out);
}